// round 15
// baseline (speedup 1.0000x reference)
#include <cuda_runtime.h>
#include <cuda_fp16.h>
#include <cstdint>
#include <math.h>

// Problem constants
#define T_TOK 2048
#define HID   2048
#define NH    16
#define DN    128
#define DR    64
#define DV    128
#define KVD   512
#define DQK   192
#define QDIM  (NH*DQK)      // 3072
#define KVADIM (KVD + DR)   // 576
#define QKVDIM (QDIM + KVADIM) // 3648
#define KVBDIM (NH*(DN+DV)) // 4096
#define ODIM  (NH*DV)       // 2048
// ATT_SCALE * log2(e): softmax runs in exp2 domain
#define ATT_SCALE2 0.10412659280059854f

// ---------------- scratch ----------------------------------------------------
__device__ __half g_hidh[(size_t)T_TOK * HID];
__device__ __half g_wqkvT[(size_t)QKVDIM * HID];   // [N][K]
__device__ __half g_wkvbT[(size_t)KVBDIM * KVD];
__device__ __half g_woT [(size_t)HID * ODIM];
__device__ __half g_qkvh[(size_t)T_TOK * QKVDIM];
__device__ __half g_kvch[(size_t)T_TOK * KVD];
__device__ __half g_kpeh[(size_t)T_TOK * DR];
__device__ __half g_kvbh[(size_t)T_TOK * KVBDIM];
__device__ __half g_attnh[(size_t)T_TOK * ODIM];

// ---------------- helpers ----------------------------------------------------
__device__ __forceinline__ uint32_t s2u(const void* p) {
    uint32_t a;
    asm("{ .reg .u64 t; cvta.to.shared.u64 t, %1; cvt.u32.u64 %0, t; }" : "=r"(a) : "l"(p));
    return a;
}
__device__ __forceinline__ void cpa16(uint32_t d, const void* s) {
    asm volatile("cp.async.cg.shared.global [%0], [%1], 16;\n" :: "r"(d), "l"(s));
}
__device__ __forceinline__ void cpa16p(uint32_t d, const void* s, bool pred) {
    int sz = pred ? 16 : 0;
    asm volatile("cp.async.cg.shared.global [%0], [%1], 16, %2;\n" :: "r"(d), "l"(s), "r"(sz));
}
#define CP_COMMIT() asm volatile("cp.async.commit_group;\n")
#define CP_WAIT(N)  asm volatile("cp.async.wait_group %0;\n" :: "n"(N))

__device__ __forceinline__ void ldsm_x4(uint32_t* r, uint32_t a) {
    asm volatile("ldmatrix.sync.aligned.m8n8.x4.shared.b16 {%0,%1,%2,%3}, [%4];"
        : "=r"(r[0]), "=r"(r[1]), "=r"(r[2]), "=r"(r[3]) : "r"(a));
}
__device__ __forceinline__ void ldsm_x4t(uint32_t* r, uint32_t a) {
    asm volatile("ldmatrix.sync.aligned.m8n8.x4.trans.shared.b16 {%0,%1,%2,%3}, [%4];"
        : "=r"(r[0]), "=r"(r[1]), "=r"(r[2]), "=r"(r[3]) : "r"(a));
}
__device__ __forceinline__ void mma_h(float* c, const uint32_t* a, uint32_t b0, uint32_t b1) {
    asm volatile(
        "mma.sync.aligned.m16n8k16.row.col.f32.f16.f16.f32 "
        "{%0,%1,%2,%3}, {%4,%5,%6,%7}, {%8,%9}, {%0,%1,%2,%3};\n"
        : "+f"(c[0]), "+f"(c[1]), "+f"(c[2]), "+f"(c[3])
        : "r"(a[0]), "r"(a[1]), "r"(a[2]), "r"(a[3]), "r"(b0), "r"(b1));
}
__device__ __forceinline__ uint32_t packh2(float x, float y) {
    __half2 h = __floats2half2_rn(x, y);
    return *(uint32_t*)&h;
}
__device__ __forceinline__ float ex2(float x) {
    float r;
    asm("ex2.approx.f32 %0, %1;" : "=f"(r) : "f"(x));
    return r;
}

// ---------------- prepass: weight transpose + hidden convert (one launch) ----
#define W0_NT (QDIM/32)
#define W0_CNT (W0_NT*(HID/32))      // 6144
#define W1_NT (KVADIM/32)
#define W1_CNT (W1_NT*(HID/32))      // 1152
#define W2_NT (KVBDIM/32)
#define W2_CNT (W2_NT*(KVD/32))      // 2048
#define W3_NT (HID/32)
#define W3_CNT (W3_NT*(ODIM/32))     // 4096
#define TW_BLOCKS (W0_CNT+W1_CNT+W2_CNT+W3_CNT)  // 13440
#define CONV_BLOCKS 1024
#define PRE_BLOCKS (TW_BLOCKS + CONV_BLOCKS)

__global__ __launch_bounds__(256) void prepass(const float* __restrict__ wq,
                                               const float* __restrict__ wkva,
                                               const float* __restrict__ wkvb,
                                               const float* __restrict__ wo,
                                               const float4* __restrict__ hid) {
    int idx = blockIdx.x;
    if (idx >= TW_BLOCKS) {
        const int n = T_TOK * HID / 4;
        uint2* dst = (uint2*)g_hidh;
        for (int i = (idx - TW_BLOCKS) * 256 + threadIdx.x; i < n; i += CONV_BLOCKS * 256) {
            float4 v = hid[i];
            dst[i] = make_uint2(packh2(v.x, v.y), packh2(v.z, v.w));
        }
        return;
    }
    const float* src;
    __half* dst;
    int K, N, NT;
    if (idx < W0_CNT) { src = wq; dst = g_wqkvT; K = HID; N = QDIM; NT = W0_NT; }
    else if ((idx -= W0_CNT) < W1_CNT) { src = wkva; dst = g_wqkvT + (size_t)QDIM * HID; K = HID; N = KVADIM; NT = W1_NT; }
    else if ((idx -= W1_CNT) < W2_CNT) { src = wkvb; dst = g_wkvbT; K = KVD; N = KVBDIM; NT = W2_NT; }
    else { idx -= W2_CNT; src = wo; dst = g_woT; K = ODIM; N = HID; NT = W3_NT; }
    int n0 = (idx % NT) * 32, k0 = (idx / NT) * 32;
    __shared__ float t[32][33];
    int tx = threadIdx.x & 31;
    int tyy = threadIdx.x >> 5;
#pragma unroll
    for (int j = 0; j < 32; j += 8)
        t[tyy + j][tx] = src[(size_t)(k0 + tyy + j) * N + n0 + tx];
    __syncthreads();
#pragma unroll
    for (int j = 0; j < 32; j += 8)
        dst[(size_t)(n0 + tyy + j) * K + k0 + tx] = __float2half_rn(t[tx][tyy + j]);
}

// ---------------- fp16 GEMM: C[M,N] = A[M,K] @ Bt[N,K]^T ---------------------
// 128x128 CTA tile, 4 warps (2x2, 64x64 warp tiles), BK=64 halves, 3 stages.
// Pitch 72 halves (144B row stride -> 8-row ldmatrix hits banks 0,4,..,28).
#define PH 72
#define STG (128 * PH)
#define GEMM_SMEM (3 * 2 * STG * 2)   // 110,592 B

__global__ __launch_bounds__(128, 2) void gemm_h(const __half* __restrict__ A,
                                                 const __half* __restrict__ Bt,
                                                 float* __restrict__ Cf,
                                                 __half* __restrict__ Ch,
                                                 int M, int N, int K) {
    extern __shared__ __half smh[];
    __half* As = smh;
    __half* Bs = smh + 3 * STG;
    const uint32_t as_u = s2u(As);
    const uint32_t bs_u = s2u(Bs);

    const int tid = threadIdx.x;
    const int lane = tid & 31;
    const int wid = tid >> 5;
    const int g = lane >> 2;
    const int tg = lane & 3;
    const int wm = wid & 1;
    const int wn = wid >> 1;
    const int crow = blockIdx.y * 128;
    const int ccol = blockIdx.x * 128;

    const int lrow = tid >> 3;          // 0..15 (+16*i)
    const int lcol = (tid & 7) << 3;    // 0..56 halves
    const int nk = K >> 6;              // BK = 64

    float acc[4][8][4];
#pragma unroll
    for (int mt = 0; mt < 4; mt++)
#pragma unroll
        for (int nt = 0; nt < 8; nt++)
#pragma unroll
            for (int c = 0; c < 4; c++) acc[mt][nt][c] = 0.f;

    auto issue = [&](int kt) {
        int buf = kt % 3;
        int k0 = kt << 6;
        uint32_t au = as_u + (uint32_t)buf * STG * 2;
        uint32_t bu = bs_u + (uint32_t)buf * STG * 2;
#pragma unroll
        for (int i = 0; i < 8; i++) {
            int r = lrow + 16 * i;
            cpa16(au + ((r * PH + lcol) << 1),
                  A + (size_t)(crow + r) * K + k0 + lcol);
            cpa16p(bu + ((r * PH + lcol) << 1),
                   Bt + (size_t)(ccol + r) * K + k0 + lcol, (ccol + r) < N);
        }
    };

    issue(0); CP_COMMIT();
    issue(1); CP_COMMIT();

    const int arow = lane & 15;
    const int acol = (lane >> 4) << 3;
    const int brow = (lane & 7) + ((lane >> 4) << 3);
    const int bcol = ((lane >> 3) & 1) << 3;

    for (int kt = 0; kt < nk; kt++) {
        CP_WAIT(1);
        __syncthreads();
        if (kt + 2 < nk) issue(kt + 2);
        CP_COMMIT();

        int buf = kt % 3;
        uint32_t ab = as_u + (uint32_t)buf * STG * 2;
        uint32_t bb = bs_u + (uint32_t)buf * STG * 2;
#pragma unroll
        for (int ks = 0; ks < 4; ks++) {
            int k = ks << 4;
            uint32_t af[4][4], bf[4][4];
#pragma unroll
            for (int mt = 0; mt < 4; mt++)
                ldsm_x4(af[mt], ab + (((wm * 64 + mt * 16 + arow) * PH + k + acol) << 1));
#pragma unroll
            for (int np = 0; np < 4; np++)
                ldsm_x4(bf[np], bb + (((wn * 64 + np * 16 + brow) * PH + k + bcol) << 1));
#pragma unroll
            for (int mt = 0; mt < 4; mt++)
#pragma unroll
                for (int nt = 0; nt < 8; nt++)
                    mma_h(acc[mt][nt], af[mt],
                          bf[nt >> 1][(nt & 1) * 2], bf[nt >> 1][(nt & 1) * 2 + 1]);
        }
    }

#pragma unroll
    for (int mt = 0; mt < 4; mt++) {
        int row = crow + wm * 64 + mt * 16 + g;
#pragma unroll
        for (int nt = 0; nt < 8; nt++) {
            int col = ccol + wn * 64 + nt * 8 + tg * 2;
            if (col < N) {
                if (Ch) {
                    *(uint32_t*)&Ch[(size_t)row * N + col] =
                        packh2(acc[mt][nt][0], acc[mt][nt][1]);
                    *(uint32_t*)&Ch[(size_t)(row + 8) * N + col] =
                        packh2(acc[mt][nt][2], acc[mt][nt][3]);
                } else {
                    *(float2*)&Cf[(size_t)row * N + col] =
                        make_float2(acc[mt][nt][0], acc[mt][nt][1]);
                    *(float2*)&Cf[(size_t)(row + 8) * N + col] =
                        make_float2(acc[mt][nt][2], acc[mt][nt][3]);
                }
            }
        }
    }
}

// ---------------- RMSNorm + RoPE (fp16 in, fp16 out) -------------------------
__global__ __launch_bounds__(256) void norm_rope(const int* __restrict__ positions,
                                                 const float* __restrict__ lnw) {
    int t   = blockIdx.x;
    int tid = threadIdx.x;
    const __half* kvrow = g_qkvh + (size_t)t * QKVDIM + QDIM;

    float ss = 0.f;
    for (int i = tid; i < KVD; i += 256) {
        float v = __half2float(kvrow[i]);
        ss += v * v;
    }
#pragma unroll
    for (int o = 16; o > 0; o >>= 1) ss += __shfl_xor_sync(0xFFFFFFFFu, ss, o);
    __shared__ float red[8];
    if ((tid & 31) == 0) red[tid >> 5] = ss;
    __syncthreads();
    float tot = 0.f;
#pragma unroll
    for (int w = 0; w < 8; w++) tot += red[w];
    float inv = rsqrtf(tot * (1.f / KVD) + 1e-6f);

    for (int i = tid; i < KVD; i += 256)
        g_kvch[(size_t)t * KVD + i] = __float2half_rn(__half2float(kvrow[i]) * inv * lnw[i]);

    float pos = (float)positions[t];

    for (int i = tid; i < DR / 2; i += 256) {
        float invf = (float)exp(-((double)(2 * i) / (double)DR) * 9.210340371976184);
        float f = pos * invf;
        float c = cosf(f), s = sinf(f);
        __half2 hv = *(__half2*)&kvrow[KVD + 2 * i];
        float x1 = __low2float(hv), x2 = __high2float(hv);
        *(uint32_t*)&g_kpeh[(size_t)t * DR + 2 * i] =
            packh2(x1 * c - x2 * s, x2 * c + x1 * s);
    }

    for (int idx = tid; idx < NH * (DR / 2); idx += 256) {
        int h = idx / (DR / 2);
        int i = idx % (DR / 2);
        float invf = (float)exp(-((double)(2 * i) / (double)DR) * 9.210340371976184);
        float f = pos * invf;
        float c = cosf(f), s = sinf(f);
        uint32_t* qp = (uint32_t*)&g_qkvh[(size_t)t * QKVDIM + h * DQK + DN + 2 * i];
        __half2 hv = *(__half2*)qp;
        float x1 = __low2float(hv), x2 = __high2float(hv);
        *qp = packh2(x1 * c - x2 * s, x2 * c + x1 * s);
    }
}

// ---------------- flash attention, fp16 mma, BQ=64, 128 thr, 2 CTAs/SM -------
#define BQ 64
#define BKT 64
#define QPH 200
#define VPH 136
#define ATT_SMEM ((BQ * QPH + BKT * QPH + BKT * VPH) * 2)

__global__ __launch_bounds__(128, 2) void attn_h() {
    extern __shared__ __half smh2[];
    __half* Qs = smh2;
    __half* Ks = Qs + BQ * QPH;
    __half* Vs = Ks + BKT * QPH;
    const uint32_t qs_u = s2u(Qs);
    const uint32_t ks_u = s2u(Ks);
    const uint32_t vs_u = s2u(Vs);

    const int bid = blockIdx.x;
    const int qb = 31 - (bid >> 4);   // heavy q-blocks first
    const int h  = bid & 15;
    const int q0 = qb * BQ;
    const int tid = threadIdx.x;
    const int lane = tid & 31;
    const int wid = tid >> 5;         // 0..3
    const int g = lane >> 2;
    const int tg = lane & 3;
    const int m0 = wid * 16;

#pragma unroll
    for (int i = 0; i < 12; i++) {
        int c = tid + 128 * i;
        int r = c / 24, cc = c % 24;
        cpa16(qs_u + ((r * QPH + cc * 8) << 1),
              g_qkvh + (size_t)(q0 + r) * QKVDIM + h * DQK + cc * 8);
    }
    CP_COMMIT();

    auto issueK = [&](int t0) {
#pragma unroll
        for (int i = 0; i < 12; i++) {
            int c = tid + 128 * i;
            int r = c / 24, cc = c % 24;
            const __half* src = (cc < 16)
                ? g_kvbh + (size_t)(t0 + r) * KVBDIM + h * 256 + cc * 8
                : g_kpeh + (size_t)(t0 + r) * DR + (cc - 16) * 8;
            cpa16(ks_u + ((r * QPH + cc * 8) << 1), src);
        }
    };
    auto issueV = [&](int t0) {
#pragma unroll
        for (int i = 0; i < 8; i++) {
            int c = tid + 128 * i;
            int r = c >> 4, cc = c & 15;
            cpa16(vs_u + ((r * VPH + cc * 8) << 1),
                  g_kvbh + (size_t)(t0 + r) * KVBDIM + h * 256 + DN + cc * 8);
        }
    };

    issueK(0); CP_COMMIT();

    float m_i[2] = {-1e30f, -1e30f};
    float l_i[2] = {0.f, 0.f};
    float oacc[16][4];
#pragma unroll
    for (int nt = 0; nt < 16; nt++)
#pragma unroll
        for (int c = 0; c < 4; c++) oacc[nt][c] = 0.f;

    const int r0 = q0 + m0 + g;
    const int r1 = r0 + 8;
    const int nkb = qb + 1;

    const int arow = lane & 15;
    const int acol = (lane >> 4) << 3;
    const int brow = (lane & 7) + ((lane >> 4) << 3);
    const int bcol = ((lane >> 3) & 1) << 3;
    const int vrow = (lane & 7) + (((lane >> 3) & 1) << 3);
    const int vcol = (lane >> 4) << 3;

    for (int kb = 0; kb < nkb; kb++) {
        int k0 = kb * BKT;
        issueV(k0); CP_COMMIT();
        CP_WAIT(1);
        __syncthreads();

        float sacc[8][4];
#pragma unroll
        for (int nt = 0; nt < 8; nt++)
#pragma unroll
            for (int c = 0; c < 4; c++) sacc[nt][c] = 0.f;
#pragma unroll
        for (int kc = 0; kc < 12; kc++) {
            int k = kc * 16;
            uint32_t af[4], bf[4][4];
            ldsm_x4(af, qs_u + (((m0 + arow) * QPH + k + acol) << 1));
#pragma unroll
            for (int np = 0; np < 4; np++)
                ldsm_x4(bf[np], ks_u + (((np * 16 + brow) * QPH + k + bcol) << 1));
#pragma unroll
            for (int nt = 0; nt < 8; nt++)
                mma_h(sacc[nt], af, bf[nt >> 1][(nt & 1) * 2], bf[nt >> 1][(nt & 1) * 2 + 1]);
        }

        CP_WAIT(0);
        __syncthreads();
        if (kb + 1 < nkb) issueK(k0 + BKT);
        CP_COMMIT();

        // scale (exp2 domain) + causal mask
#pragma unroll
        for (int nt = 0; nt < 8; nt++) {
            int c0i = k0 + nt * 8 + tg * 2;
            sacc[nt][0] = (c0i     <= r0) ? sacc[nt][0] * ATT_SCALE2 : -1e30f;
            sacc[nt][1] = (c0i + 1 <= r0) ? sacc[nt][1] * ATT_SCALE2 : -1e30f;
            sacc[nt][2] = (c0i     <= r1) ? sacc[nt][2] * ATT_SCALE2 : -1e30f;
            sacc[nt][3] = (c0i + 1 <= r1) ? sacc[nt][3] * ATT_SCALE2 : -1e30f;
        }

        float mx0 = -1e30f, mx1 = -1e30f;
#pragma unroll
        for (int nt = 0; nt < 8; nt++) {
            mx0 = fmaxf(mx0, fmaxf(sacc[nt][0], sacc[nt][1]));
            mx1 = fmaxf(mx1, fmaxf(sacc[nt][2], sacc[nt][3]));
        }
        mx0 = fmaxf(mx0, __shfl_xor_sync(0xFFFFFFFFu, mx0, 1));
        mx0 = fmaxf(mx0, __shfl_xor_sync(0xFFFFFFFFu, mx0, 2));
        mx1 = fmaxf(mx1, __shfl_xor_sync(0xFFFFFFFFu, mx1, 1));
        mx1 = fmaxf(mx1, __shfl_xor_sync(0xFFFFFFFFu, mx1, 2));

        float nm0 = fmaxf(m_i[0], mx0);
        float nm1 = fmaxf(m_i[1], mx1);
        float al0 = ex2(m_i[0] - nm0);
        float al1 = ex2(m_i[1] - nm1);
        m_i[0] = nm0; m_i[1] = nm1;

        float rs0 = 0.f, rs1 = 0.f;
#pragma unroll
        for (int nt = 0; nt < 8; nt++) {
            float p0 = ex2(sacc[nt][0] - nm0);
            float p1 = ex2(sacc[nt][1] - nm0);
            float p2 = ex2(sacc[nt][2] - nm1);
            float p3 = ex2(sacc[nt][3] - nm1);
            sacc[nt][0] = p0; sacc[nt][1] = p1; sacc[nt][2] = p2; sacc[nt][3] = p3;
            rs0 += p0 + p1; rs1 += p2 + p3;
        }
        rs0 += __shfl_xor_sync(0xFFFFFFFFu, rs0, 1);
        rs0 += __shfl_xor_sync(0xFFFFFFFFu, rs0, 2);
        rs1 += __shfl_xor_sync(0xFFFFFFFFu, rs1, 1);
        rs1 += __shfl_xor_sync(0xFFFFFFFFu, rs1, 2);
        l_i[0] = l_i[0] * al0 + rs0;
        l_i[1] = l_i[1] * al1 + rs1;

#pragma unroll
        for (int nt = 0; nt < 16; nt++) {
            oacc[nt][0] *= al0; oacc[nt][1] *= al0;
            oacc[nt][2] *= al1; oacc[nt][3] *= al1;
        }

#pragma unroll
        for (int kc = 0; kc < 4; kc++) {
            uint32_t pa[4];
            pa[0] = packh2(sacc[2 * kc][0],     sacc[2 * kc][1]);
            pa[1] = packh2(sacc[2 * kc][2],     sacc[2 * kc][3]);
            pa[2] = packh2(sacc[2 * kc + 1][0], sacc[2 * kc + 1][1]);
            pa[3] = packh2(sacc[2 * kc + 1][2], sacc[2 * kc + 1][3]);
            int k = kc * 16;
#pragma unroll
            for (int np = 0; np < 8; np++) {
                uint32_t vf[4];
                ldsm_x4t(vf, vs_u + (((k + vrow) * VPH + np * 16 + vcol) << 1));
                mma_h(oacc[np * 2],     pa, vf[0], vf[1]);
                mma_h(oacc[np * 2 + 1], pa, vf[2], vf[3]);
            }
        }
        __syncthreads();
    }

    float inv0 = 1.f / l_i[0];
    float inv1 = 1.f / l_i[1];
#pragma unroll
    for (int nt = 0; nt < 16; nt++) {
        int col = h * DV + nt * 8 + tg * 2;
        *(uint32_t*)&g_attnh[(size_t)r0 * ODIM + col] =
            packh2(oacc[nt][0] * inv0, oacc[nt][1] * inv0);
        *(uint32_t*)&g_attnh[(size_t)r1 * ODIM + col] =
            packh2(oacc[nt][2] * inv1, oacc[nt][3] * inv1);
    }
}

// ---------------- launch ----------------------------------------------------
extern "C" void kernel_launch(void* const* d_in, const int* in_sizes, int n_in,
                              void* d_out, int out_size) {
    const int*   positions = (const int*)d_in[0];
    const float* hidden    = (const float*)d_in[1];
    const float* w_q       = (const float*)d_in[2];
    const float* w_kv_a    = (const float*)d_in[3];
    const float* kv_a_ln_w = (const float*)d_in[4];
    const float* w_kv_b    = (const float*)d_in[5];
    const float* w_o       = (const float*)d_in[6];
    float* out = (float*)d_out;

    __half *p_hidh, *p_wqkvT, *p_wkvbT, *p_woT;
    __half *p_qkvh, *p_kvch, *p_kvbh, *p_attnh;
    cudaGetSymbolAddress((void**)&p_hidh,  g_hidh);
    cudaGetSymbolAddress((void**)&p_wqkvT, g_wqkvT);
    cudaGetSymbolAddress((void**)&p_wkvbT, g_wkvbT);
    cudaGetSymbolAddress((void**)&p_woT,   g_woT);
    cudaGetSymbolAddress((void**)&p_qkvh,  g_qkvh);
    cudaGetSymbolAddress((void**)&p_kvch,  g_kvch);
    cudaGetSymbolAddress((void**)&p_kvbh,  g_kvbh);
    cudaGetSymbolAddress((void**)&p_attnh, g_attnh);

    cudaFuncSetAttribute(gemm_h, cudaFuncAttributeMaxDynamicSharedMemorySize, GEMM_SMEM);
    cudaFuncSetAttribute(attn_h, cudaFuncAttributeMaxDynamicSharedMemorySize, ATT_SMEM);

    // 0. prepass: weight transpose + hidden convert, single launch
    prepass<<<PRE_BLOCKS, 256>>>(w_q, w_kv_a, w_kv_b, w_o, (const float4*)hidden);

    // 1. [q | kv] = hid @ [w_q | w_kv_a]   (fp16 out, N=3648)
    gemm_h<<<dim3((QKVDIM + 127) / 128, T_TOK / 128), 128, GEMM_SMEM>>>(
        p_hidh, p_wqkvT, nullptr, p_qkvh, T_TOK, QKVDIM, HID);
    // 2. rmsnorm + rope
    norm_rope<<<T_TOK, 256>>>(positions, kv_a_ln_w);
    // 3. kvb = kv_c @ w_kv_b (fp16 out)
    gemm_h<<<dim3(KVBDIM / 128, T_TOK / 128), 128, GEMM_SMEM>>>(
        p_kvch, p_wkvbT, nullptr, p_kvbh, T_TOK, KVBDIM, KVD);
    // 4. attention (512 CTAs, heavy-first, 2 CTAs/SM)
    attn_h<<<T_TOK / BQ * NH, 128, ATT_SMEM>>>();
    // 5. out = attn @ w_o (fp32 out)
    gemm_h<<<dim3(HID / 128, T_TOK / 128), 128, GEMM_SMEM>>>(
        p_attnh, p_woT, out, nullptr, T_TOK, HID, ODIM);
}

// round 16
// speedup vs baseline: 1.0295x; 1.0295x over previous
#include <cuda_runtime.h>
#include <cuda_fp16.h>
#include <cstdint>
#include <math.h>

// Problem constants
#define T_TOK 2048
#define HID   2048
#define NH    16
#define DN    128
#define DR    64
#define DV    128
#define KVD   512
#define DQK   192
#define QDIM  (NH*DQK)      // 3072
#define KVADIM (KVD + DR)   // 576
#define QKVDIM (QDIM + KVADIM) // 3648
#define KVBDIM (NH*(DN+DV)) // 4096
#define ODIM  (NH*DV)       // 2048
// ATT_SCALE * log2(e): softmax runs in exp2 domain
#define ATT_SCALE2 0.10412659280059854f

// ---------------- scratch ----------------------------------------------------
__device__ __half g_hidh[(size_t)T_TOK * HID];
__device__ __half g_wqkvT[(size_t)QKVDIM * HID];   // [N][K]
__device__ __half g_wkvbT[(size_t)KVBDIM * KVD];
__device__ __half g_woT [(size_t)HID * ODIM];
__device__ __half g_qkvh[(size_t)T_TOK * QKVDIM];
__device__ __half g_kvch[(size_t)T_TOK * KVD];
__device__ __half g_kpeh[(size_t)T_TOK * DR];
__device__ __half g_kvbh[(size_t)T_TOK * KVBDIM];
__device__ __half g_attnh[(size_t)T_TOK * ODIM];

// ---------------- helpers ----------------------------------------------------
__device__ __forceinline__ uint32_t s2u(const void* p) {
    uint32_t a;
    asm("{ .reg .u64 t; cvta.to.shared.u64 t, %1; cvt.u32.u64 %0, t; }" : "=r"(a) : "l"(p));
    return a;
}
__device__ __forceinline__ void cpa16(uint32_t d, const void* s) {
    asm volatile("cp.async.cg.shared.global [%0], [%1], 16;\n" :: "r"(d), "l"(s));
}
__device__ __forceinline__ void cpa16p(uint32_t d, const void* s, bool pred) {
    int sz = pred ? 16 : 0;
    asm volatile("cp.async.cg.shared.global [%0], [%1], 16, %2;\n" :: "r"(d), "l"(s), "r"(sz));
}
#define CP_COMMIT() asm volatile("cp.async.commit_group;\n")
#define CP_WAIT(N)  asm volatile("cp.async.wait_group %0;\n" :: "n"(N))

__device__ __forceinline__ void ldsm_x4(uint32_t* r, uint32_t a) {
    asm volatile("ldmatrix.sync.aligned.m8n8.x4.shared.b16 {%0,%1,%2,%3}, [%4];"
        : "=r"(r[0]), "=r"(r[1]), "=r"(r[2]), "=r"(r[3]) : "r"(a));
}
__device__ __forceinline__ void ldsm_x4t(uint32_t* r, uint32_t a) {
    asm volatile("ldmatrix.sync.aligned.m8n8.x4.trans.shared.b16 {%0,%1,%2,%3}, [%4];"
        : "=r"(r[0]), "=r"(r[1]), "=r"(r[2]), "=r"(r[3]) : "r"(a));
}
__device__ __forceinline__ void mma_h(float* c, const uint32_t* a, uint32_t b0, uint32_t b1) {
    asm volatile(
        "mma.sync.aligned.m16n8k16.row.col.f32.f16.f16.f32 "
        "{%0,%1,%2,%3}, {%4,%5,%6,%7}, {%8,%9}, {%0,%1,%2,%3};\n"
        : "+f"(c[0]), "+f"(c[1]), "+f"(c[2]), "+f"(c[3])
        : "r"(a[0]), "r"(a[1]), "r"(a[2]), "r"(a[3]), "r"(b0), "r"(b1));
}
__device__ __forceinline__ uint32_t packh2(float x, float y) {
    __half2 h = __floats2half2_rn(x, y);
    return *(uint32_t*)&h;
}
__device__ __forceinline__ float ex2(float x) {
    float r;
    asm("ex2.approx.f32 %0, %1;" : "=f"(r) : "f"(x));
    return r;
}

// ---------------- prepass: weight transpose + hidden convert (one launch) ----
#define W0_NT (QDIM/32)
#define W0_CNT (W0_NT*(HID/32))      // 6144
#define W1_NT (KVADIM/32)
#define W1_CNT (W1_NT*(HID/32))      // 1152
#define W2_NT (KVBDIM/32)
#define W2_CNT (W2_NT*(KVD/32))      // 2048
#define W3_NT (HID/32)
#define W3_CNT (W3_NT*(ODIM/32))     // 4096
#define TW_BLOCKS (W0_CNT+W1_CNT+W2_CNT+W3_CNT)  // 13440
#define CONV_BLOCKS 1024
#define PRE_BLOCKS (TW_BLOCKS + CONV_BLOCKS)

__global__ __launch_bounds__(256) void prepass(const float* __restrict__ wq,
                                               const float* __restrict__ wkva,
                                               const float* __restrict__ wkvb,
                                               const float* __restrict__ wo,
                                               const float4* __restrict__ hid) {
    int idx = blockIdx.x;
    if (idx >= TW_BLOCKS) {
        const int n = T_TOK * HID / 4;
        uint2* dst = (uint2*)g_hidh;
        for (int i = (idx - TW_BLOCKS) * 256 + threadIdx.x; i < n; i += CONV_BLOCKS * 256) {
            float4 v = hid[i];
            dst[i] = make_uint2(packh2(v.x, v.y), packh2(v.z, v.w));
        }
        return;
    }
    const float* src;
    __half* dst;
    int K, N, NT;
    if (idx < W0_CNT) { src = wq; dst = g_wqkvT; K = HID; N = QDIM; NT = W0_NT; }
    else if ((idx -= W0_CNT) < W1_CNT) { src = wkva; dst = g_wqkvT + (size_t)QDIM * HID; K = HID; N = KVADIM; NT = W1_NT; }
    else if ((idx -= W1_CNT) < W2_CNT) { src = wkvb; dst = g_wkvbT; K = KVD; N = KVBDIM; NT = W2_NT; }
    else { idx -= W2_CNT; src = wo; dst = g_woT; K = ODIM; N = HID; NT = W3_NT; }
    int n0 = (idx % NT) * 32, k0 = (idx / NT) * 32;
    __shared__ float t[32][33];
    int tx = threadIdx.x & 31;
    int tyy = threadIdx.x >> 5;
#pragma unroll
    for (int j = 0; j < 32; j += 8)
        t[tyy + j][tx] = src[(size_t)(k0 + tyy + j) * N + n0 + tx];
    __syncthreads();
#pragma unroll
    for (int j = 0; j < 32; j += 8)
        dst[(size_t)(n0 + tyy + j) * K + k0 + tx] = __float2half_rn(t[tx][tyy + j]);
}

// ---------------- fp16 GEMM: C[M,N] = A[M,K] @ Bt[N,K]^T ---------------------
// 128x128 CTA tile, 4 warps (2x2, 64x64 warp tiles), BK=32, 4-stage cp.async.
#define PH 40
#define STG (128 * PH)
#define NSTG 4
#define GEMM_SMEM (NSTG * 2 * STG * 2)   // 163,840 B

__global__ __launch_bounds__(128, 2) void gemm_h(const __half* __restrict__ A,
                                                 const __half* __restrict__ Bt,
                                                 float* __restrict__ Cf,
                                                 __half* __restrict__ Ch,
                                                 int M, int N, int K) {
    extern __shared__ __half smh[];
    __half* As = smh;
    __half* Bs = smh + NSTG * STG;
    const uint32_t as_u = s2u(As);
    const uint32_t bs_u = s2u(Bs);

    const int tid = threadIdx.x;
    const int lane = tid & 31;
    const int wid = tid >> 5;
    const int g = lane >> 2;
    const int tg = lane & 3;
    const int wm = wid & 1;
    const int wn = wid >> 1;
    const int crow = blockIdx.y * 128;
    const int ccol = blockIdx.x * 128;

    const int lrow = tid >> 2;
    const int lcol = (tid & 3) << 3;
    const int nk = K >> 5;

    float acc[4][8][4];
#pragma unroll
    for (int mt = 0; mt < 4; mt++)
#pragma unroll
        for (int nt = 0; nt < 8; nt++)
#pragma unroll
            for (int c = 0; c < 4; c++) acc[mt][nt][c] = 0.f;

    auto issue = [&](int kt) {
        int buf = kt % NSTG;
        int k0 = kt << 5;
        uint32_t au = as_u + (uint32_t)buf * STG * 2;
        uint32_t bu = bs_u + (uint32_t)buf * STG * 2;
#pragma unroll
        for (int i = 0; i < 4; i++) {
            int r = lrow + 32 * i;
            cpa16(au + ((r * PH + lcol) << 1),
                  A + (size_t)(crow + r) * K + k0 + lcol);
            cpa16p(bu + ((r * PH + lcol) << 1),
                   Bt + (size_t)(ccol + r) * K + k0 + lcol, (ccol + r) < N);
        }
    };

    issue(0); CP_COMMIT();
    issue(1); CP_COMMIT();
    issue(2); CP_COMMIT();

    const int arow = lane & 15;
    const int acol = (lane >> 4) << 3;
    const int brow = (lane & 7) + ((lane >> 4) << 3);
    const int bcol = ((lane >> 3) & 1) << 3;

    for (int kt = 0; kt < nk; kt++) {
        CP_WAIT(2);
        __syncthreads();
        if (kt + 3 < nk) issue(kt + 3);
        CP_COMMIT();

        int buf = kt % NSTG;
        uint32_t ab = as_u + (uint32_t)buf * STG * 2;
        uint32_t bb = bs_u + (uint32_t)buf * STG * 2;
#pragma unroll
        for (int ks = 0; ks < 2; ks++) {
            int k = ks << 4;
            uint32_t af[4][4], bf[4][4];
#pragma unroll
            for (int mt = 0; mt < 4; mt++)
                ldsm_x4(af[mt], ab + (((wm * 64 + mt * 16 + arow) * PH + k + acol) << 1));
#pragma unroll
            for (int np = 0; np < 4; np++)
                ldsm_x4(bf[np], bb + (((wn * 64 + np * 16 + brow) * PH + k + bcol) << 1));
#pragma unroll
            for (int mt = 0; mt < 4; mt++)
#pragma unroll
                for (int nt = 0; nt < 8; nt++)
                    mma_h(acc[mt][nt], af[mt],
                          bf[nt >> 1][(nt & 1) * 2], bf[nt >> 1][(nt & 1) * 2 + 1]);
        }
    }

#pragma unroll
    for (int mt = 0; mt < 4; mt++) {
        int row = crow + wm * 64 + mt * 16 + g;
#pragma unroll
        for (int nt = 0; nt < 8; nt++) {
            int col = ccol + wn * 64 + nt * 8 + tg * 2;
            if (col < N) {
                if (Ch) {
                    *(uint32_t*)&Ch[(size_t)row * N + col] =
                        packh2(acc[mt][nt][0], acc[mt][nt][1]);
                    *(uint32_t*)&Ch[(size_t)(row + 8) * N + col] =
                        packh2(acc[mt][nt][2], acc[mt][nt][3]);
                } else {
                    *(float2*)&Cf[(size_t)row * N + col] =
                        make_float2(acc[mt][nt][0], acc[mt][nt][1]);
                    *(float2*)&Cf[(size_t)(row + 8) * N + col] =
                        make_float2(acc[mt][nt][2], acc[mt][nt][3]);
                }
            }
        }
    }
}

// ---------------- RMSNorm + RoPE (fp16 in, fp16 out) -------------------------
__global__ __launch_bounds__(256) void norm_rope(const int* __restrict__ positions,
                                                 const float* __restrict__ lnw) {
    int t   = blockIdx.x;
    int tid = threadIdx.x;
    const __half* kvrow = g_qkvh + (size_t)t * QKVDIM + QDIM;

    float ss = 0.f;
    for (int i = tid; i < KVD; i += 256) {
        float v = __half2float(kvrow[i]);
        ss += v * v;
    }
#pragma unroll
    for (int o = 16; o > 0; o >>= 1) ss += __shfl_xor_sync(0xFFFFFFFFu, ss, o);
    __shared__ float red[8];
    if ((tid & 31) == 0) red[tid >> 5] = ss;
    __syncthreads();
    float tot = 0.f;
#pragma unroll
    for (int w = 0; w < 8; w++) tot += red[w];
    float inv = rsqrtf(tot * (1.f / KVD) + 1e-6f);

    for (int i = tid; i < KVD; i += 256)
        g_kvch[(size_t)t * KVD + i] = __float2half_rn(__half2float(kvrow[i]) * inv * lnw[i]);

    float pos = (float)positions[t];

    for (int i = tid; i < DR / 2; i += 256) {
        float invf = (float)exp(-((double)(2 * i) / (double)DR) * 9.210340371976184);
        float f = pos * invf;
        float c = cosf(f), s = sinf(f);
        __half2 hv = *(__half2*)&kvrow[KVD + 2 * i];
        float x1 = __low2float(hv), x2 = __high2float(hv);
        *(uint32_t*)&g_kpeh[(size_t)t * DR + 2 * i] =
            packh2(x1 * c - x2 * s, x2 * c + x1 * s);
    }

    for (int idx = tid; idx < NH * (DR / 2); idx += 256) {
        int h = idx / (DR / 2);
        int i = idx % (DR / 2);
        float invf = (float)exp(-((double)(2 * i) / (double)DR) * 9.210340371976184);
        float f = pos * invf;
        float c = cosf(f), s = sinf(f);
        uint32_t* qp = (uint32_t*)&g_qkvh[(size_t)t * QKVDIM + h * DQK + DN + 2 * i];
        __half2 hv = *(__half2*)qp;
        float x1 = __low2float(hv), x2 = __high2float(hv);
        *qp = packh2(x1 * c - x2 * s, x2 * c + x1 * s);
    }
}

// ---------------- flash attention, fp16 mma, BQ=64, 128 thr, 2 CTAs/SM -------
#define BQ 64
#define BKT 64
#define QPH 200
#define VPH 136
#define ATT_SMEM ((BQ * QPH + BKT * QPH + BKT * VPH) * 2)

__global__ __launch_bounds__(128, 2) void attn_h() {
    extern __shared__ __half smh2[];
    __half* Qs = smh2;
    __half* Ks = Qs + BQ * QPH;
    __half* Vs = Ks + BKT * QPH;
    const uint32_t qs_u = s2u(Qs);
    const uint32_t ks_u = s2u(Ks);
    const uint32_t vs_u = s2u(Vs);

    const int bid = blockIdx.x;
    const int qb = 31 - (bid >> 4);   // heavy q-blocks first
    const int h  = bid & 15;
    const int q0 = qb * BQ;
    const int tid = threadIdx.x;
    const int lane = tid & 31;
    const int wid = tid >> 5;         // 0..3
    const int g = lane >> 2;
    const int tg = lane & 3;
    const int m0 = wid * 16;

#pragma unroll
    for (int i = 0; i < 12; i++) {
        int c = tid + 128 * i;
        int r = c / 24, cc = c % 24;
        cpa16(qs_u + ((r * QPH + cc * 8) << 1),
              g_qkvh + (size_t)(q0 + r) * QKVDIM + h * DQK + cc * 8);
    }
    CP_COMMIT();

    auto issueK = [&](int t0) {
#pragma unroll
        for (int i = 0; i < 12; i++) {
            int c = tid + 128 * i;
            int r = c / 24, cc = c % 24;
            const __half* src = (cc < 16)
                ? g_kvbh + (size_t)(t0 + r) * KVBDIM + h * 256 + cc * 8
                : g_kpeh + (size_t)(t0 + r) * DR + (cc - 16) * 8;
            cpa16(ks_u + ((r * QPH + cc * 8) << 1), src);
        }
    };
    auto issueV = [&](int t0) {
#pragma unroll
        for (int i = 0; i < 8; i++) {
            int c = tid + 128 * i;
            int r = c >> 4, cc = c & 15;
            cpa16(vs_u + ((r * VPH + cc * 8) << 1),
                  g_kvbh + (size_t)(t0 + r) * KVBDIM + h * 256 + DN + cc * 8);
        }
    };

    issueK(0); CP_COMMIT();

    float m_i[2] = {-1e30f, -1e30f};
    float l_i[2] = {0.f, 0.f};
    float oacc[16][4];
#pragma unroll
    for (int nt = 0; nt < 16; nt++)
#pragma unroll
        for (int c = 0; c < 4; c++) oacc[nt][c] = 0.f;

    const int r0 = q0 + m0 + g;
    const int r1 = r0 + 8;
    const int nkb = qb + 1;

    const int arow = lane & 15;
    const int acol = (lane >> 4) << 3;
    const int brow = (lane & 7) + ((lane >> 4) << 3);
    const int bcol = ((lane >> 3) & 1) << 3;
    const int vrow = (lane & 7) + (((lane >> 3) & 1) << 3);
    const int vcol = (lane >> 4) << 3;

    for (int kb = 0; kb < nkb; kb++) {
        int k0 = kb * BKT;
        issueV(k0); CP_COMMIT();
        CP_WAIT(1);
        __syncthreads();

        float sacc[8][4];
#pragma unroll
        for (int nt = 0; nt < 8; nt++)
#pragma unroll
            for (int c = 0; c < 4; c++) sacc[nt][c] = 0.f;
#pragma unroll
        for (int kc = 0; kc < 12; kc++) {
            int k = kc * 16;
            uint32_t af[4], bf[4][4];
            ldsm_x4(af, qs_u + (((m0 + arow) * QPH + k + acol) << 1));
#pragma unroll
            for (int np = 0; np < 4; np++)
                ldsm_x4(bf[np], ks_u + (((np * 16 + brow) * QPH + k + bcol) << 1));
#pragma unroll
            for (int nt = 0; nt < 8; nt++)
                mma_h(sacc[nt], af, bf[nt >> 1][(nt & 1) * 2], bf[nt >> 1][(nt & 1) * 2 + 1]);
        }

        CP_WAIT(0);
        __syncthreads();
        if (kb + 1 < nkb) issueK(k0 + BKT);
        CP_COMMIT();

        // scale (exp2 domain) + causal mask
#pragma unroll
        for (int nt = 0; nt < 8; nt++) {
            int c0i = k0 + nt * 8 + tg * 2;
            sacc[nt][0] = (c0i     <= r0) ? sacc[nt][0] * ATT_SCALE2 : -1e30f;
            sacc[nt][1] = (c0i + 1 <= r0) ? sacc[nt][1] * ATT_SCALE2 : -1e30f;
            sacc[nt][2] = (c0i     <= r1) ? sacc[nt][2] * ATT_SCALE2 : -1e30f;
            sacc[nt][3] = (c0i + 1 <= r1) ? sacc[nt][3] * ATT_SCALE2 : -1e30f;
        }

        float mx0 = -1e30f, mx1 = -1e30f;
#pragma unroll
        for (int nt = 0; nt < 8; nt++) {
            mx0 = fmaxf(mx0, fmaxf(sacc[nt][0], sacc[nt][1]));
            mx1 = fmaxf(mx1, fmaxf(sacc[nt][2], sacc[nt][3]));
        }
        mx0 = fmaxf(mx0, __shfl_xor_sync(0xFFFFFFFFu, mx0, 1));
        mx0 = fmaxf(mx0, __shfl_xor_sync(0xFFFFFFFFu, mx0, 2));
        mx1 = fmaxf(mx1, __shfl_xor_sync(0xFFFFFFFFu, mx1, 1));
        mx1 = fmaxf(mx1, __shfl_xor_sync(0xFFFFFFFFu, mx1, 2));

        float nm0 = fmaxf(m_i[0], mx0);
        float nm1 = fmaxf(m_i[1], mx1);
        float al0 = ex2(m_i[0] - nm0);
        float al1 = ex2(m_i[1] - nm1);
        m_i[0] = nm0; m_i[1] = nm1;

        float rs0 = 0.f, rs1 = 0.f;
#pragma unroll
        for (int nt = 0; nt < 8; nt++) {
            float p0 = ex2(sacc[nt][0] - nm0);
            float p1 = ex2(sacc[nt][1] - nm0);
            float p2 = ex2(sacc[nt][2] - nm1);
            float p3 = ex2(sacc[nt][3] - nm1);
            sacc[nt][0] = p0; sacc[nt][1] = p1; sacc[nt][2] = p2; sacc[nt][3] = p3;
            rs0 += p0 + p1; rs1 += p2 + p3;
        }
        rs0 += __shfl_xor_sync(0xFFFFFFFFu, rs0, 1);
        rs0 += __shfl_xor_sync(0xFFFFFFFFu, rs0, 2);
        rs1 += __shfl_xor_sync(0xFFFFFFFFu, rs1, 1);
        rs1 += __shfl_xor_sync(0xFFFFFFFFu, rs1, 2);
        l_i[0] = l_i[0] * al0 + rs0;
        l_i[1] = l_i[1] * al1 + rs1;

#pragma unroll
        for (int nt = 0; nt < 16; nt++) {
            oacc[nt][0] *= al0; oacc[nt][1] *= al0;
            oacc[nt][2] *= al1; oacc[nt][3] *= al1;
        }

#pragma unroll
        for (int kc = 0; kc < 4; kc++) {
            uint32_t pa[4];
            pa[0] = packh2(sacc[2 * kc][0],     sacc[2 * kc][1]);
            pa[1] = packh2(sacc[2 * kc][2],     sacc[2 * kc][3]);
            pa[2] = packh2(sacc[2 * kc + 1][0], sacc[2 * kc + 1][1]);
            pa[3] = packh2(sacc[2 * kc + 1][2], sacc[2 * kc + 1][3]);
            int k = kc * 16;
#pragma unroll
            for (int np = 0; np < 8; np++) {
                uint32_t vf[4];
                ldsm_x4t(vf, vs_u + (((k + vrow) * VPH + np * 16 + vcol) << 1));
                mma_h(oacc[np * 2],     pa, vf[0], vf[1]);
                mma_h(oacc[np * 2 + 1], pa, vf[2], vf[3]);
            }
        }
        __syncthreads();
    }

    float inv0 = 1.f / l_i[0];
    float inv1 = 1.f / l_i[1];
#pragma unroll
    for (int nt = 0; nt < 16; nt++) {
        int col = h * DV + nt * 8 + tg * 2;
        *(uint32_t*)&g_attnh[(size_t)r0 * ODIM + col] =
            packh2(oacc[nt][0] * inv0, oacc[nt][1] * inv0);
        *(uint32_t*)&g_attnh[(size_t)r1 * ODIM + col] =
            packh2(oacc[nt][2] * inv1, oacc[nt][3] * inv1);
    }
}

// ---------------- launch ----------------------------------------------------
extern "C" void kernel_launch(void* const* d_in, const int* in_sizes, int n_in,
                              void* d_out, int out_size) {
    const int*   positions = (const int*)d_in[0];
    const float* hidden    = (const float*)d_in[1];
    const float* w_q       = (const float*)d_in[2];
    const float* w_kv_a    = (const float*)d_in[3];
    const float* kv_a_ln_w = (const float*)d_in[4];
    const float* w_kv_b    = (const float*)d_in[5];
    const float* w_o       = (const float*)d_in[6];
    float* out = (float*)d_out;

    __half *p_hidh, *p_wqkvT, *p_wkvbT, *p_woT;
    __half *p_qkvh, *p_kvch, *p_kvbh, *p_attnh;
    cudaGetSymbolAddress((void**)&p_hidh,  g_hidh);
    cudaGetSymbolAddress((void**)&p_wqkvT, g_wqkvT);
    cudaGetSymbolAddress((void**)&p_wkvbT, g_wkvbT);
    cudaGetSymbolAddress((void**)&p_woT,   g_woT);
    cudaGetSymbolAddress((void**)&p_qkvh,  g_qkvh);
    cudaGetSymbolAddress((void**)&p_kvch,  g_kvch);
    cudaGetSymbolAddress((void**)&p_kvbh,  g_kvbh);
    cudaGetSymbolAddress((void**)&p_attnh, g_attnh);

    cudaFuncSetAttribute(gemm_h, cudaFuncAttributeMaxDynamicSharedMemorySize, GEMM_SMEM);
    cudaFuncSetAttribute(attn_h, cudaFuncAttributeMaxDynamicSharedMemorySize, ATT_SMEM);

    // 0. prepass: weight transpose + hidden convert, single launch
    prepass<<<PRE_BLOCKS, 256>>>(w_q, w_kv_a, w_kv_b, w_o, (const float4*)hidden);

    // 1. [q | kv] = hid @ [w_q | w_kv_a]   (fp16 out, N=3648)
    gemm_h<<<dim3((QKVDIM + 127) / 128, T_TOK / 128), 128, GEMM_SMEM>>>(
        p_hidh, p_wqkvT, nullptr, p_qkvh, T_TOK, QKVDIM, HID);
    // 2. rmsnorm + rope
    norm_rope<<<T_TOK, 256>>>(positions, kv_a_ln_w);
    // 3. kvb = kv_c @ w_kv_b (fp16 out)
    gemm_h<<<dim3(KVBDIM / 128, T_TOK / 128), 128, GEMM_SMEM>>>(
        p_kvch, p_wkvbT, nullptr, p_kvbh, T_TOK, KVBDIM, KVD);
    // 4. attention (512 CTAs, heavy-first, 2 CTAs/SM)
    attn_h<<<T_TOK / BQ * NH, 128, ATT_SMEM>>>();
    // 5. out = attn @ w_o (fp32 out)
    gemm_h<<<dim3(HID / 128, T_TOK / 128), 128, GEMM_SMEM>>>(
        p_attnh, p_woT, out, nullptr, T_TOK, HID, ODIM);
}